// round 15
// baseline (speedup 1.0000x reference)
#include <cuda_runtime.h>
#include <cuda_fp16.h>
#include <cstdint>
#include <math.h>

#define BB 16
#define TT 4096
#define JJ 17
#define CC 128
#define HH 512
#define KK 2048
#define BT (BB*TT)

#define SEL_ELEMS (BB*KK*JJ*CC)   // 71303168
#define IDX_ELEMS (BB*KK)         // 32768

// ---- scratch (static device arrays; no allocation allowed) ----
__device__ float g_stn[BT*CC];          // layernormed joint-mean  [B*T, C]
__device__ float g_gc_part[BB*32*CC];   // partial sums for global context
__device__ float g_gc[BB*CC];           // global context  [B, C]
__device__ float g_scores[BT];          // raw MLP scores  [B*T]
__device__ int   g_selidx[BB*KK];       // selected indices, ascending per batch
__device__ float g_gate[BB*KK];         // 1 + 0.1*sigmoid(score)
// W1 scaled by 256, split into 2 fp16 components, [k][h] layout
__device__ __align__(16) __half g_Wh[CC*HH];
__device__ __align__(16) __half g_Wm[CC*HH];

__device__ __forceinline__ float gelu_exact(float x) {
    return 0.5f * x * (1.0f + erff(x * 0.70710678118654752440f));
}

__device__ __forceinline__ uint32_t smem_u32(const void* p) {
    uint32_t a;
    asm("{ .reg .u64 t; cvta.to.shared.u64 t, %1; cvt.u32.u64 %0, t; }"
        : "=r"(a) : "l"(p));
    return a;
}
__device__ __forceinline__ void ldmatrix_x4(uint32_t* r, uint32_t addr) {
    asm volatile("ldmatrix.sync.aligned.m8n8.x4.shared.b16 {%0,%1,%2,%3}, [%4];"
                 : "=r"(r[0]), "=r"(r[1]), "=r"(r[2]), "=r"(r[3]) : "r"(addr));
}
__device__ __forceinline__ void ldmatrix_x4_t(uint32_t* r, uint32_t addr) {
    asm volatile("ldmatrix.sync.aligned.m8n8.x4.trans.shared.b16 {%0,%1,%2,%3}, [%4];"
                 : "=r"(r[0]), "=r"(r[1]), "=r"(r[2]), "=r"(r[3]) : "r"(addr));
}
__device__ __forceinline__ void mma16816(float* d, const uint32_t* a,
                                         uint32_t b0, uint32_t b1) {
    asm volatile(
        "mma.sync.aligned.m16n8k16.row.col.f32.f16.f16.f32 "
        "{%0,%1,%2,%3}, {%4,%5,%6,%7}, {%8,%9}, {%0,%1,%2,%3};"
        : "+f"(d[0]), "+f"(d[1]), "+f"(d[2]), "+f"(d[3])
        : "r"(a[0]), "r"(a[1]), "r"(a[2]), "r"(a[3]), "r"(b0), "r"(b1));
}
__device__ __forceinline__ void cp_async16(uint32_t dst, const void* src) {
    asm volatile("cp.async.cg.shared.global [%0], [%1], 16;"
                 :: "r"(dst), "l"(src));
}
#define CP_COMMIT() asm volatile("cp.async.commit_group;" ::: "memory")
#define CP_WAIT(N)  asm volatile("cp.async.wait_group %0;" :: "n"(N) : "memory")

// ---------------- Kernel 1: joint mean + LayerNorm (warp per token) --------
__global__ void __launch_bounds__(256) mean_ln_kernel(
    const float* __restrict__ tokens,
    const float* __restrict__ ln_w,
    const float* __restrict__ ln_b)
{
    int bt   = blockIdx.x * 8 + (threadIdx.x >> 5);
    int lane = threadIdx.x & 31;

    const float4* src = (const float4*)(tokens + (size_t)bt * (JJ*CC)) + lane;
    float4 s = make_float4(0.f, 0.f, 0.f, 0.f);
#pragma unroll
    for (int j = 0; j < JJ; ++j) {
        float4 v = src[j * 32];
        s.x += v.x; s.y += v.y; s.z += v.z; s.w += v.w;
    }
    const float inv17 = 1.0f/17.0f;
    s.x *= inv17; s.y *= inv17; s.z *= inv17; s.w *= inv17;

    float m = s.x + s.y + s.z + s.w;
    float q = s.x*s.x + s.y*s.y + s.z*s.z + s.w*s.w;
#pragma unroll
    for (int o = 16; o; o >>= 1) {
        m += __shfl_xor_sync(0xffffffffu, m, o);
        q += __shfl_xor_sync(0xffffffffu, q, o);
    }
    float mu  = m * (1.0f/128.0f);
    float var = q * (1.0f/128.0f) - mu*mu;
    float inv = rsqrtf(var + 1e-5f);

    float4 wv = *((const float4*)ln_w + lane);
    float4 bv = *((const float4*)ln_b + lane);
    float4 o4;
    o4.x = (s.x - mu) * inv * wv.x + bv.x;
    o4.y = (s.y - mu) * inv * wv.y + bv.y;
    o4.z = (s.z - mu) * inv * wv.z + bv.z;
    o4.w = (s.w - mu) * inv * wv.w + bv.w;
    *((float4*)(g_stn + (size_t)bt*CC) + lane) = o4;
}

// ---------------- Kernel 2: gc partial reduce ----------------
__global__ void __launch_bounds__(128) gc_partial_kernel()
{
    int b = blockIdx.x, chunk = blockIdx.y, c = threadIdx.x;
    const float* p = g_stn + ((size_t)(b*TT + chunk*128))*CC + c;
    float s = 0.f;
#pragma unroll 8
    for (int t = 0; t < 128; ++t) s += p[(size_t)t*CC];
    g_gc_part[(b*32 + chunk)*CC + c] = s;
}

// ---------------- Kernel 3: gc final + W1 fp16 split (fused launch) ----------
__global__ void __launch_bounds__(128) gcfinal_splitw_kernel(
    const float* __restrict__ W1)
{
    if (blockIdx.x < 16) {
        int b = blockIdx.x, c = threadIdx.x;
        float s = 0.f;
#pragma unroll
        for (int k = 0; k < 32; ++k) s += g_gc_part[(b*32 + k)*CC + c];
        g_gc[b*CC + c] = s * (1.0f/4096.0f);
    } else {
        int base = (blockIdx.x - 16) * 128 + threadIdx.x;
#pragma unroll
        for (int rep = 0; rep < 2; ++rep) {
            int idx = base + rep*32768;       // = k*512 + h
            float w = W1[idx] * 256.0f;
            __half wh = __float2half_rn(w);
            __half wm = __float2half_rn(w - __half2float(wh));
            g_Wh[idx] = wh; g_Wm[idx] = wm;
        }
    }
}

// ---------------- Kernel 4: MLP scoring, fp16 split, 3 products ------------
// 64-token tiles (grid 1024), 256 threads, H in 4 chunks of 128.
// Warp w (of 8): token half (w&1)*32, h-quarter (w>>1)*32.
// Fat tile: 24 MMA / 8 LDSM per warp-kstep; regs cap 128 (256thr x occ 2).
#define XPB 272               // X row pitch bytes
#define WPB 272               // W row pitch bytes (128 fp16 = 256B + 16 pad)
#define OFF_B1   0
#define OFF_W2   2048
#define OFF_PART 4096         // 4*64 floats = 1024 B
#define OFF_X    5120         // 2 * 64*272 = 34816
#define XCOMP    (64*XPB)     // 17408
#define OFF_W    39936        // 2 comp * 128*272 = 69632 (single buffer)
#define WCOMP    (128*WPB)    // 34816
#define MLP_SMEM 109568

__global__ void __launch_bounds__(256, 2) mlp_kernel(
    const float* __restrict__ b1v,
    const float* __restrict__ W2v,
    const float* __restrict__ b2v)
{
    extern __shared__ unsigned char smraw[];
    uint32_t sb = smem_u32(smraw);
    float* s_b1  = (float*)(smraw + OFF_B1);
    float* s_w2  = (float*)(smraw + OFF_W2);
    float* s_prt = (float*)(smraw + OFF_PART);

    int tid = threadIdx.x, w = tid >> 5, lane = tid & 31;
    int g0 = blockIdx.x * 64, b = g0 >> 12;

    s_b1[tid] = b1v[tid]; s_b1[tid+256] = b1v[tid+256];
    s_w2[tid] = W2v[tid]; s_w2[tid+256] = W2v[tid+256];

    // ---- W chunk stage (cp.async, [k][128h] per comp, padded rows) ----
    const __half* gW[2] = {g_Wh, g_Wm};
#define STAGE_W(c) do {                                                        \
    for (int i = tid; i < 4096; i += 256) {                                    \
        int comp = i >> 11, rem = i & 2047, k = rem >> 4, ch = rem & 15;       \
        uint32_t dst = sb + OFF_W + comp*WCOMP + k*WPB + ch*16;                \
        cp_async16(dst, gW[comp] + (size_t)k*HH + (c)*128 + ch*8);             \
    }                                                                          \
    CP_COMMIT();                                                               \
} while (0)

    STAGE_W(0);

    // ---- stage X: fp16 split of 16*(x+gc), 2 components, padded rows ----
#pragma unroll
    for (int r = 0; r < 8; ++r) {
        int i  = r*256 + tid;          // 64 t x 32 k-quads
        int t  = i >> 5;
        int kq = (i & 31) * 4;
        float4 x4 = *(const float4*)(g_stn + (size_t)(g0 + t)*CC + kq);
        float4 g4 = *(const float4*)(g_gc + b*CC + kq);
        float xv[4] = {(x4.x + g4.x)*16.0f, (x4.y + g4.y)*16.0f,
                       (x4.z + g4.z)*16.0f, (x4.w + g4.w)*16.0f};
        unsigned long long ph = 0, pm = 0;
#pragma unroll
        for (int e = 0; e < 4; ++e) {
            float x = xv[e];
            __half hh = __float2half_rn(x);
            __half hm = __float2half_rn(x - __half2float(hh));
            ph |= (unsigned long long)__half_as_ushort(hh) << (16*e);
            pm |= (unsigned long long)__half_as_ushort(hm) << (16*e);
        }
        int off = t*XPB + kq*2;
        *(unsigned long long*)(smraw + OFF_X + 0*XCOMP + off) = ph;
        *(unsigned long long*)(smraw + OFF_X + 1*XCOMP + off) = pm;
    }

    int th = w & 1, nq = w >> 1;   // token half (2, 32t each) x h-quarter (4, 32h)
    int tb = th * 32;
    int g  = lane >> 2, tig = lane & 3;

    // A addresses: comp x (rows tb+0..15 / tb+16..31), col half (lane>>4)
    uint32_t a_addr[2];
#pragma unroll
    for (int comp = 0; comp < 2; ++comp)
        a_addr[comp] = sb + OFF_X + comp*XCOMP + (tb + (lane & 15))*XPB
                     + (lane >> 4)*16;
    uint32_t wb_base = sb + OFF_W + (lane & 15)*WPB + nq*64 + (lane >> 4)*16;

    float sum[4] = {0.f, 0.f, 0.f, 0.f};   // [th-sub(2) x row(g,g+8)]
    const float RS = 1.0f/4096.0f;

    for (int c = 0; c < 4; ++c) {
        CP_WAIT(0);
        __syncthreads();    // W(c) visible everywhere; X visible (c=0)

        float acc[2][4][4];   // token sub-half x n-tile x frag
#pragma unroll
        for (int i = 0; i < 2; ++i)
#pragma unroll
            for (int nt = 0; nt < 4; ++nt)
#pragma unroll
                for (int q = 0; q < 4; ++q) acc[i][nt][q] = 0.f;

#pragma unroll
        for (int ks = 0; ks < 8; ++ks) {
            uint32_t A[2][2][4];   // comp x sub-half
#pragma unroll
            for (int comp = 0; comp < 2; ++comp) {
                ldmatrix_x4(A[comp][0], a_addr[comp] + ks*32);
                ldmatrix_x4(A[comp][1], a_addr[comp] + 16*XPB + ks*32);
            }

            uint32_t wb = wb_base + ks*16*WPB;
            // comp h of W: products Xh*Wh and Xm*Wh, both token halves
#pragma unroll
            for (int pr = 0; pr < 2; ++pr) {
                uint32_t Bf[4];
                ldmatrix_x4_t(Bf, wb + pr*32);
                int nt0 = pr*2, nt1 = pr*2 + 1;
#pragma unroll
                for (int i = 0; i < 2; ++i) {
                    mma16816(acc[i][nt0], A[0][i], Bf[0], Bf[1]);
                    mma16816(acc[i][nt1], A[0][i], Bf[2], Bf[3]);
                    mma16816(acc[i][nt0], A[1][i], Bf[0], Bf[1]);
                    mma16816(acc[i][nt1], A[1][i], Bf[2], Bf[3]);
                }
            }
            // comp m of W: product Xh*Wm only
#pragma unroll
            for (int pr = 0; pr < 2; ++pr) {
                uint32_t Bf[4];
                ldmatrix_x4_t(Bf, wb + WCOMP + pr*32);
                int nt0 = pr*2, nt1 = pr*2 + 1;
#pragma unroll
                for (int i = 0; i < 2; ++i) {
                    mma16816(acc[i][nt0], A[0][i], Bf[0], Bf[1]);
                    mma16816(acc[i][nt1], A[0][i], Bf[2], Bf[3]);
                }
            }
        }

        __syncthreads();            // all reads of W(c) done
        if (c < 3) STAGE_W(c + 1);  // restage overlaps the gelu epilogue below

        // epilogue: rescale + gelu + dot(W2)  (touches only b1/w2/regs)
#pragma unroll
        for (int i = 0; i < 2; ++i) {
#pragma unroll
            for (int nt = 0; nt < 4; ++nt) {
                int cg = c*128 + nq*32 + nt*8 + tig*2;
                float ba = s_b1[cg], bb = s_b1[cg+1];
                float wa = s_w2[cg], wbv = s_w2[cg+1];
                sum[i*2]   += gelu_exact(acc[i][nt][0]*RS + ba)*wa
                            + gelu_exact(acc[i][nt][1]*RS + bb)*wbv;
                sum[i*2+1] += gelu_exact(acc[i][nt][2]*RS + ba)*wa
                            + gelu_exact(acc[i][nt][3]*RS + bb)*wbv;
            }
        }
    }

    // quad reduction (lanes with same row)
#pragma unroll
    for (int i = 0; i < 4; ++i) {
        sum[i] += __shfl_xor_sync(0xffffffffu, sum[i], 1);
        sum[i] += __shfl_xor_sync(0xffffffffu, sum[i], 2);
    }
    if (tig == 0) {
        s_prt[nq*64 + tb + g]          = sum[0];
        s_prt[nq*64 + tb + g + 8]      = sum[1];
        s_prt[nq*64 + tb + 16 + g]     = sum[2];
        s_prt[nq*64 + tb + 16 + g + 8] = sum[3];
    }
    __syncthreads();
    if (tid < 64) {
        float s = b2v[0];
#pragma unroll
        for (int qq = 0; qq < 4; ++qq) s += s_prt[qq*64 + tid];
        g_scores[g0 + tid] = s;
    }
}

// ---------------- Kernel 5: normalize + radix-select top-k + compact -------
__device__ __forceinline__ unsigned long long mk_key(float f, int i) {
    unsigned u = __float_as_uint(f);
    u = (u & 0x80000000u) ? ~u : (u | 0x80000000u);  // order-preserving
    return (((unsigned long long)(~u)) << 32) | (unsigned)i; // top-K = K smallest keys
}

#define TOPK_SMEM 50688
__global__ void __launch_bounds__(1024) topk_kernel(
    float* __restrict__ out_idx, float* __restrict__ out_scores)
{
    extern __shared__ unsigned char shraw[];
    float*              sc   = (float*)shraw;                          // [4096]
    unsigned long long* key  = (unsigned long long*)(shraw + 16384);   // [4096]
    int*                hist = (int*)(shraw + 49152);                  // [256]
    int*                redi = (int*)(shraw + 50176);                  // [64]
    float*              redf = (float*)(shraw + 50432);                // [64]

    int b = blockIdx.x, tid = threadIdx.x;
    int lane = tid & 31, wid = tid >> 5;
    int base4 = tid * 4;

    // ---- normalize scores ----
    float4 v = *(const float4*)(g_scores + b*TT + base4);
    float s = v.x + v.y + v.z + v.w;
#pragma unroll
    for (int o = 16; o; o >>= 1) s += __shfl_down_sync(0xffffffffu, s, o);
    if (lane == 0) redf[wid] = s;
    __syncthreads();
    if (tid == 0) {
        float a = 0.f;
        for (int i = 0; i < 32; ++i) a += redf[i];
        redf[32] = a * (1.0f/TT);
    }
    __syncthreads();
    float mean = redf[32];
    float d0 = v.x-mean, d1 = v.y-mean, d2 = v.z-mean, d3 = v.w-mean;
    float q = d0*d0 + d1*d1 + d2*d2 + d3*d3;
    __syncthreads();
#pragma unroll
    for (int o = 16; o; o >>= 1) q += __shfl_down_sync(0xffffffffu, q, o);
    if (lane == 0) redf[wid] = q;
    __syncthreads();
    if (tid == 0) {
        float a = 0.f;
        for (int i = 0; i < 32; ++i) a += redf[i];
        redf[33] = 1.0f / (sqrtf(a * (1.0f/TT)) + 1e-6f);
    }
    __syncthreads();
    float inv = redf[33];
    float n0 = d0*inv, n1 = d1*inv, n2 = d2*inv, n3 = d3*inv;

    sc[base4+0] = n0; sc[base4+1] = n1; sc[base4+2] = n2; sc[base4+3] = n3;
    *(float4*)(out_scores + b*TT + base4) = make_float4(n0, n1, n2, n3);
    key[base4+0] = mk_key(n0, base4+0);
    key[base4+1] = mk_key(n1, base4+1);
    key[base4+2] = mk_key(n2, base4+2);
    key[base4+3] = mk_key(n3, base4+3);
    if (tid == 0) redi[41] = KK;     // K' for radix select
    __syncthreads();

    // ---- radix select: exact K-th smallest 64-bit key, 8x8-bit passes ----
    unsigned long long pref = 0;
    for (int p = 7; p >= 0; --p) {
        if (tid < 256) hist[tid] = 0;
        __syncthreads();
#pragma unroll
        for (int qq = 0; qq < 4; ++qq) {
            unsigned long long k = key[base4 + qq];
            bool m = (p == 7) || ((k >> ((p+1)*8)) == pref);
            if (m) atomicAdd(&hist[(int)((k >> (p*8)) & 255)], 1);
        }
        __syncthreads();
        if (wid == 0) {
            int Kp = redi[41];
            int local[8], lsum = 0;
#pragma unroll
            for (int j = 0; j < 8; ++j) { local[j] = hist[lane*8 + j]; lsum += local[j]; }
            int sscan = lsum;
#pragma unroll
            for (int o = 1; o < 32; o <<= 1) {
                int vv = __shfl_up_sync(0xffffffffu, sscan, o);
                if (lane >= o) sscan += vv;
            }
            int below = sscan - lsum;              // keys in lower lanes' bins
            if (below < Kp && Kp <= sscan) {       // crossing lane (unique)
                int cum = below, t = 0, nk = 0;
#pragma unroll
                for (int j = 0; j < 8; ++j) {
                    if (cum + local[j] >= Kp) { t = lane*8 + j; nk = Kp - cum; break; }
                    cum += local[j];
                }
                redi[40] = t; redi[41] = nk;
            }
        }
        __syncthreads();
        pref = (pref << 8) | (unsigned)redi[40];
    }
    unsigned long long T = pref;    // exact K-th smallest key

    // ---- compact ascending by token index ----
    int f0 = key[base4+0] <= T, f1 = key[base4+1] <= T,
        f2 = key[base4+2] <= T, f3 = key[base4+3] <= T;
    int tot = f0 + f1 + f2 + f3;
    int x = tot;
#pragma unroll
    for (int o = 1; o < 32; o <<= 1) {
        int y = __shfl_up_sync(0xffffffffu, x, o);
        if (lane >= o) x += y;
    }
    if (lane == 31) redi[wid] = x;
    __syncthreads();
    if (wid == 0) {
        int y = redi[lane];
        int z = y;
#pragma unroll
        for (int o = 1; o < 32; o <<= 1) {
            int w2 = __shfl_up_sync(0xffffffffu, z, o);
            if (lane >= o) z += w2;
        }
        redi[32 + lane] = z - y;   // exclusive
    }
    __syncthreads();
    int off = redi[32 + wid] + (x - tot);

    int flags[4] = {f0, f1, f2, f3};
#pragma unroll
    for (int qq = 0; qq < 4; ++qq) {
        if (flags[qq]) {
            int idx = base4 + qq;
            int pos = b*KK + off;
            g_selidx[pos] = idx;
            out_idx[pos]  = (float)idx;
            g_gate[pos]   = 1.0f + 0.1f * (1.0f / (1.0f + expf(-sc[idx])));
            ++off;
        }
    }
}

// ---------------- Kernel 6: gather + gate ----------------
__global__ void __launch_bounds__(256) gather_kernel(
    const float* __restrict__ tokens, float* __restrict__ out_sel)
{
    int bk  = blockIdx.x;          // b*K + kk
    int b   = bk >> 11;
    int idx = g_selidx[bk];
    float gate = g_gate[bk];
    const float4* src = (const float4*)(tokens + ((size_t)(b*TT + idx)) * (JJ*CC));
    float4* dst = (float4*)(out_sel + (size_t)bk * (JJ*CC));
#pragma unroll 2
    for (int i = threadIdx.x; i < (JJ*CC)/4; i += 256) {
        float4 v = src[i];
        v.x *= gate; v.y *= gate; v.z *= gate; v.w *= gate;
        dst[i] = v;
    }
}

// ---------------- launch ----------------
extern "C" void kernel_launch(void* const* d_in, const int* in_sizes, int n_in,
                              void* d_out, int out_size)
{
    const float* tokens = (const float*)d_in[0];
    const float* ln_w   = (const float*)d_in[1];
    const float* ln_b   = (const float*)d_in[2];
    const float* W1     = (const float*)d_in[3];
    const float* b1     = (const float*)d_in[4];
    const float* W2     = (const float*)d_in[5];
    const float* b2     = (const float*)d_in[6];

    float* out        = (float*)d_out;
    float* out_sel    = out;                       // [B,K,J,C]
    float* out_idx    = out + SEL_ELEMS;           // [B,K]
    float* out_scores = out_idx + IDX_ELEMS;       // [B,T]

    cudaFuncSetAttribute(mlp_kernel,
        cudaFuncAttributeMaxDynamicSharedMemorySize, MLP_SMEM);
    cudaFuncSetAttribute(topk_kernel,
        cudaFuncAttributeMaxDynamicSharedMemorySize, TOPK_SMEM);

    mean_ln_kernel<<<BT/8, 256>>>(tokens, ln_w, ln_b);
    gc_partial_kernel<<<dim3(BB, 32), 128>>>();
    gcfinal_splitw_kernel<<<272, 128>>>(W1);
    mlp_kernel<<<BT/64, 256, MLP_SMEM>>>(b1, W2, b2);   // 4th launch -> ncu capture
    topk_kernel<<<BB, 1024, TOPK_SMEM>>>(out_idx, out_scores);
    gather_kernel<<<BB*KK, 256>>>(tokens, out_sel);
}

// round 16
// speedup vs baseline: 1.0682x; 1.0682x over previous
#include <cuda_runtime.h>
#include <cuda_fp16.h>
#include <cstdint>
#include <math.h>

#define BB 16
#define TT 4096
#define JJ 17
#define CC 128
#define HH 512
#define KK 2048
#define BT (BB*TT)

#define SEL_ELEMS (BB*KK*JJ*CC)   // 71303168
#define IDX_ELEMS (BB*KK)         // 32768

// ---- scratch (static device arrays; no allocation allowed) ----
__device__ float g_stn[BT*CC];          // layernormed joint-mean  [B*T, C]
__device__ float g_gc_part[(BT/8)*CC];  // per-block st_n partials [8192, C]
__device__ float g_gc[BB*CC];           // global context  [B, C]
__device__ float g_scores[BT];          // raw MLP scores  [B*T]
__device__ int   g_selidx[BB*KK];       // selected indices, ascending per batch
__device__ float g_gate[BB*KK];         // 1 + 0.1*sigmoid(score)
// W1 scaled by 256, split into 2 fp16 components, [k][h] layout
__device__ __align__(16) __half g_Wh[CC*HH];
__device__ __align__(16) __half g_Wm[CC*HH];

__device__ __forceinline__ float gelu_exact(float x) {
    return 0.5f * x * (1.0f + erff(x * 0.70710678118654752440f));
}

__device__ __forceinline__ uint32_t smem_u32(const void* p) {
    uint32_t a;
    asm("{ .reg .u64 t; cvta.to.shared.u64 t, %1; cvt.u32.u64 %0, t; }"
        : "=r"(a) : "l"(p));
    return a;
}
__device__ __forceinline__ void ldmatrix_x4(uint32_t* r, uint32_t addr) {
    asm volatile("ldmatrix.sync.aligned.m8n8.x4.shared.b16 {%0,%1,%2,%3}, [%4];"
                 : "=r"(r[0]), "=r"(r[1]), "=r"(r[2]), "=r"(r[3]) : "r"(addr));
}
__device__ __forceinline__ void ldmatrix_x4_t(uint32_t* r, uint32_t addr) {
    asm volatile("ldmatrix.sync.aligned.m8n8.x4.trans.shared.b16 {%0,%1,%2,%3}, [%4];"
                 : "=r"(r[0]), "=r"(r[1]), "=r"(r[2]), "=r"(r[3]) : "r"(addr));
}
__device__ __forceinline__ void mma16816(float* d, const uint32_t* a,
                                         uint32_t b0, uint32_t b1) {
    asm volatile(
        "mma.sync.aligned.m16n8k16.row.col.f32.f16.f16.f32 "
        "{%0,%1,%2,%3}, {%4,%5,%6,%7}, {%8,%9}, {%0,%1,%2,%3};"
        : "+f"(d[0]), "+f"(d[1]), "+f"(d[2]), "+f"(d[3])
        : "r"(a[0]), "r"(a[1]), "r"(a[2]), "r"(a[3]), "r"(b0), "r"(b1));
}
__device__ __forceinline__ void cp_async16(uint32_t dst, const void* src) {
    asm volatile("cp.async.cg.shared.global [%0], [%1], 16;"
                 :: "r"(dst), "l"(src));
}
#define CP_COMMIT() asm volatile("cp.async.commit_group;" ::: "memory")
#define CP_WAIT(N)  asm volatile("cp.async.wait_group %0;" :: "n"(N) : "memory")

// ---------------- Kernel 1: joint mean + LayerNorm + gc partial ------------
// warp per token; the block (8 tokens, same batch) also reduces its st_n
// into one gc partial row, eliminating a separate 33.5MB re-read.
__global__ void __launch_bounds__(256) mean_ln_kernel(
    const float* __restrict__ tokens,
    const float* __restrict__ ln_w,
    const float* __restrict__ ln_b)
{
    __shared__ float part[8][132];
    int w    = threadIdx.x >> 5;
    int lane = threadIdx.x & 31;
    int bt   = blockIdx.x * 8 + w;

    const float4* src = (const float4*)(tokens + (size_t)bt * (JJ*CC)) + lane;
    float4 s = make_float4(0.f, 0.f, 0.f, 0.f);
#pragma unroll
    for (int j = 0; j < JJ; ++j) {
        float4 v = src[j * 32];
        s.x += v.x; s.y += v.y; s.z += v.z; s.w += v.w;
    }
    const float inv17 = 1.0f/17.0f;
    s.x *= inv17; s.y *= inv17; s.z *= inv17; s.w *= inv17;

    float m = s.x + s.y + s.z + s.w;
    float q = s.x*s.x + s.y*s.y + s.z*s.z + s.w*s.w;
#pragma unroll
    for (int o = 16; o; o >>= 1) {
        m += __shfl_xor_sync(0xffffffffu, m, o);
        q += __shfl_xor_sync(0xffffffffu, q, o);
    }
    float mu  = m * (1.0f/128.0f);
    float var = q * (1.0f/128.0f) - mu*mu;
    float inv = rsqrtf(var + 1e-5f);

    float4 wv = *((const float4*)ln_w + lane);
    float4 bv = *((const float4*)ln_b + lane);
    float4 o4;
    o4.x = (s.x - mu) * inv * wv.x + bv.x;
    o4.y = (s.y - mu) * inv * wv.y + bv.y;
    o4.z = (s.z - mu) * inv * wv.z + bv.z;
    o4.w = (s.w - mu) * inv * wv.w + bv.w;
    *((float4*)(g_stn + (size_t)bt*CC) + lane) = o4;

    *(float4*)(&part[w][lane*4]) = o4;
    __syncthreads();
    if (threadIdx.x < 128) {
        float a = 0.f;
#pragma unroll
        for (int r = 0; r < 8; ++r) a += part[r][threadIdx.x];
        g_gc_part[(size_t)blockIdx.x*CC + threadIdx.x] = a;
    }
}

// ---------------- Kernel 2: gc final reduce (512 partials per batch) -------
__global__ void __launch_bounds__(1024) gc_final_kernel()
{
    __shared__ float red[8][132];
    int b = blockIdx.x;
    int c = threadIdx.x & 127;
    int r = threadIdx.x >> 7;    // 0..7
    float s = 0.f;
#pragma unroll 8
    for (int i = r; i < 512; i += 8)
        s += g_gc_part[(size_t)(b*512 + i)*CC + c];
    red[r][c] = s;
    __syncthreads();
    if (threadIdx.x < 128) {
        float a = 0.f;
#pragma unroll
        for (int i = 0; i < 8; ++i) a += red[i][c];
        g_gc[b*CC + c] = a * (1.0f/4096.0f);
    }
}

// ---------------- Kernel 3: split 256*W1 into fp16 hi/mid, [k][h] ----------
__global__ void __launch_bounds__(256) split_w_kernel(const float* __restrict__ W1)
{
    int idx = blockIdx.x * 256 + threadIdx.x;   // = k*512 + h
    float w = W1[idx] * 256.0f;
    __half wh = __float2half_rn(w);
    __half wm = __float2half_rn(w - __half2float(wh));
    g_Wh[idx] = wh; g_Wm[idx] = wm;
}

// ---------------- Kernel 4: MLP scoring, fp16 split, 3 products ------------
// R14 geometry: 64-token tiles (grid 1024), 512 threads, H in 4 chunks of 128,
// W single-buffered -> 2 CTAs/SM; warp (of 16): tokens (w&3)*16, h-q (w>>2)*32.
#define XPB 272               // X row pitch bytes
#define WPB 272               // W row pitch bytes (128 fp16 = 256B + 16 pad)
#define OFF_B1   0
#define OFF_W2   2048
#define OFF_PART 4096         // 4*64 floats = 1024 B
#define OFF_X    5120         // 2 * 64*272 = 34816
#define XCOMP    (64*XPB)     // 17408
#define OFF_W    39936        // 2 comp * 128*272 = 69632 (single buffer)
#define WCOMP    (128*WPB)    // 34816
#define MLP_SMEM 109568

__global__ void __launch_bounds__(512, 2) mlp_kernel(
    const float* __restrict__ b1v,
    const float* __restrict__ W2v,
    const float* __restrict__ b2v)
{
    extern __shared__ unsigned char smraw[];
    uint32_t sb = smem_u32(smraw);
    float* s_b1  = (float*)(smraw + OFF_B1);
    float* s_w2  = (float*)(smraw + OFF_W2);
    float* s_prt = (float*)(smraw + OFF_PART);

    int tid = threadIdx.x, w = tid >> 5, lane = tid & 31;
    int g0 = blockIdx.x * 64, b = g0 >> 12;

    if (tid < 512) { s_b1[tid] = b1v[tid]; s_w2[tid] = W2v[tid]; }

    // ---- W chunk stage (cp.async, [k][128h] per comp, padded rows) ----
    const __half* gW[2] = {g_Wh, g_Wm};
#define STAGE_W(c) do {                                                        \
    for (int i = tid; i < 4096; i += 512) {                                    \
        int comp = i >> 11, rem = i & 2047, k = rem >> 4, ch = rem & 15;       \
        uint32_t dst = sb + OFF_W + comp*WCOMP + k*WPB + ch*16;                \
        cp_async16(dst, gW[comp] + (size_t)k*HH + (c)*128 + ch*8);             \
    }                                                                          \
    CP_COMMIT();                                                               \
} while (0)

    STAGE_W(0);

    // ---- stage X: fp16 split of 16*(x+gc), 2 components, padded rows ----
#pragma unroll
    for (int r = 0; r < 4; ++r) {
        int i  = r*512 + tid;          // 64 t x 32 k-quads
        int t  = i >> 5;
        int kq = (i & 31) * 4;
        float4 x4 = *(const float4*)(g_stn + (size_t)(g0 + t)*CC + kq);
        float4 g4 = *(const float4*)(g_gc + b*CC + kq);
        float xv[4] = {(x4.x + g4.x)*16.0f, (x4.y + g4.y)*16.0f,
                       (x4.z + g4.z)*16.0f, (x4.w + g4.w)*16.0f};
        unsigned long long ph = 0, pm = 0;
#pragma unroll
        for (int e = 0; e < 4; ++e) {
            float x = xv[e];
            __half hh = __float2half_rn(x);
            __half hm = __float2half_rn(x - __half2float(hh));
            ph |= (unsigned long long)__half_as_ushort(hh) << (16*e);
            pm |= (unsigned long long)__half_as_ushort(hm) << (16*e);
        }
        int off = t*XPB + kq*2;
        *(unsigned long long*)(smraw + OFF_X + 0*XCOMP + off) = ph;
        *(unsigned long long*)(smraw + OFF_X + 1*XCOMP + off) = pm;
    }

    int tw = w & 3, nq = w >> 2;   // token group (4) x h-quarter (4, 32h each)
    int tb = tw * 16;
    int g  = lane >> 2, tig = lane & 3;

    uint32_t a_addr[2];
#pragma unroll
    for (int comp = 0; comp < 2; ++comp)
        a_addr[comp] = sb + OFF_X + comp*XCOMP + (tb + (lane & 15))*XPB
                     + (lane >> 4)*16;

    float sum_r = 0.f, sum_r8 = 0.f;
    const float RS = 1.0f/4096.0f;

    for (int c = 0; c < 4; ++c) {
        CP_WAIT(0);
        __syncthreads();    // W(c) visible everywhere; X visible (c=0)

        float acc[4][4];
#pragma unroll
        for (int nt = 0; nt < 4; ++nt)
#pragma unroll
            for (int q = 0; q < 4; ++q) acc[nt][q] = 0.f;

#pragma unroll
        for (int ks = 0; ks < 8; ++ks) {
            uint32_t A[2][4];
#pragma unroll
            for (int comp = 0; comp < 2; ++comp)
                ldmatrix_x4(A[comp], a_addr[comp] + ks*32);

            // B base: k rows ks*16 + (lane&15); warp's 32-h quarter at nq*64 B
            uint32_t wb = sb + OFF_W
                        + (ks*16 + (lane & 15))*WPB + nq*64 + (lane >> 4)*16;
            // comp h of W: products Xh*Wh and Xm*Wh
#pragma unroll
            for (int pr = 0; pr < 2; ++pr) {
                uint32_t Bf[4];
                ldmatrix_x4_t(Bf, wb + pr*32);
                int nt0 = pr*2, nt1 = pr*2 + 1;
                mma16816(acc[nt0], A[0], Bf[0], Bf[1]);
                mma16816(acc[nt1], A[0], Bf[2], Bf[3]);
                mma16816(acc[nt0], A[1], Bf[0], Bf[1]);
                mma16816(acc[nt1], A[1], Bf[2], Bf[3]);
            }
            // comp m of W: product Xh*Wm only
#pragma unroll
            for (int pr = 0; pr < 2; ++pr) {
                uint32_t Bf[4];
                ldmatrix_x4_t(Bf, wb + WCOMP + pr*32);
                int nt0 = pr*2, nt1 = pr*2 + 1;
                mma16816(acc[nt0], A[0], Bf[0], Bf[1]);
                mma16816(acc[nt1], A[0], Bf[2], Bf[3]);
            }
        }

        __syncthreads();            // all reads of W(c) done
        if (c < 3) STAGE_W(c + 1);  // restage overlaps the gelu epilogue below

        // epilogue: rescale + gelu + dot(W2)  (touches only b1/w2/regs)
#pragma unroll
        for (int nt = 0; nt < 4; ++nt) {
            int cg = c*128 + nq*32 + nt*8 + tig*2;
            float ba = s_b1[cg], bb = s_b1[cg+1];
            float wa = s_w2[cg], wbv = s_w2[cg+1];
            sum_r  += gelu_exact(acc[nt][0]*RS + ba)*wa
                    + gelu_exact(acc[nt][1]*RS + bb)*wbv;
            sum_r8 += gelu_exact(acc[nt][2]*RS + ba)*wa
                    + gelu_exact(acc[nt][3]*RS + bb)*wbv;
        }
    }

    // quad reduction (lanes with same row)
    sum_r  += __shfl_xor_sync(0xffffffffu, sum_r, 1);
    sum_r  += __shfl_xor_sync(0xffffffffu, sum_r, 2);
    sum_r8 += __shfl_xor_sync(0xffffffffu, sum_r8, 1);
    sum_r8 += __shfl_xor_sync(0xffffffffu, sum_r8, 2);
    if (tig == 0) {
        s_prt[nq*64 + tb + g]     = sum_r;
        s_prt[nq*64 + tb + g + 8] = sum_r8;
    }
    __syncthreads();
    if (tid < 64) {
        float s = b2v[0];
#pragma unroll
        for (int qq = 0; qq < 4; ++qq) s += s_prt[qq*64 + tid];
        g_scores[g0 + tid] = s;
    }
}

// ---------------- Kernel 5: normalize + radix-select top-k + compact -------
__device__ __forceinline__ unsigned long long mk_key(float f, int i) {
    unsigned u = __float_as_uint(f);
    u = (u & 0x80000000u) ? ~u : (u | 0x80000000u);  // order-preserving
    return (((unsigned long long)(~u)) << 32) | (unsigned)i; // top-K = K smallest keys
}

#define TOPK_SMEM 50688
__global__ void __launch_bounds__(1024) topk_kernel(
    float* __restrict__ out_idx, float* __restrict__ out_scores)
{
    extern __shared__ unsigned char shraw[];
    float*              sc   = (float*)shraw;                          // [4096]
    unsigned long long* key  = (unsigned long long*)(shraw + 16384);   // [4096]
    int*                hist = (int*)(shraw + 49152);                  // [256]
    int*                redi = (int*)(shraw + 50176);                  // [64]
    float*              redf = (float*)(shraw + 50432);                // [64]

    int b = blockIdx.x, tid = threadIdx.x;
    int lane = tid & 31, wid = tid >> 5;
    int base4 = tid * 4;

    // ---- normalize scores ----
    float4 v = *(const float4*)(g_scores + b*TT + base4);
    float s = v.x + v.y + v.z + v.w;
#pragma unroll
    for (int o = 16; o; o >>= 1) s += __shfl_down_sync(0xffffffffu, s, o);
    if (lane == 0) redf[wid] = s;
    __syncthreads();
    if (tid == 0) {
        float a = 0.f;
        for (int i = 0; i < 32; ++i) a += redf[i];
        redf[32] = a * (1.0f/TT);
    }
    __syncthreads();
    float mean = redf[32];
    float d0 = v.x-mean, d1 = v.y-mean, d2 = v.z-mean, d3 = v.w-mean;
    float q = d0*d0 + d1*d1 + d2*d2 + d3*d3;
    __syncthreads();
#pragma unroll
    for (int o = 16; o; o >>= 1) q += __shfl_down_sync(0xffffffffu, q, o);
    if (lane == 0) redf[wid] = q;
    __syncthreads();
    if (tid == 0) {
        float a = 0.f;
        for (int i = 0; i < 32; ++i) a += redf[i];
        redf[33] = 1.0f / (sqrtf(a * (1.0f/TT)) + 1e-6f);
    }
    __syncthreads();
    float inv = redf[33];
    float n0 = d0*inv, n1 = d1*inv, n2 = d2*inv, n3 = d3*inv;

    sc[base4+0] = n0; sc[base4+1] = n1; sc[base4+2] = n2; sc[base4+3] = n3;
    *(float4*)(out_scores + b*TT + base4) = make_float4(n0, n1, n2, n3);
    key[base4+0] = mk_key(n0, base4+0);
    key[base4+1] = mk_key(n1, base4+1);
    key[base4+2] = mk_key(n2, base4+2);
    key[base4+3] = mk_key(n3, base4+3);
    if (tid == 0) redi[41] = KK;     // K' for radix select
    __syncthreads();

    // ---- radix select: exact K-th smallest 64-bit key, 8x8-bit passes ----
    unsigned long long pref = 0;
    for (int p = 7; p >= 0; --p) {
        if (tid < 256) hist[tid] = 0;
        __syncthreads();
#pragma unroll
        for (int qq = 0; qq < 4; ++qq) {
            unsigned long long k = key[base4 + qq];
            bool m = (p == 7) || ((k >> ((p+1)*8)) == pref);
            if (m) atomicAdd(&hist[(int)((k >> (p*8)) & 255)], 1);
        }
        __syncthreads();
        if (wid == 0) {
            int Kp = redi[41];
            int local[8], lsum = 0;
#pragma unroll
            for (int j = 0; j < 8; ++j) { local[j] = hist[lane*8 + j]; lsum += local[j]; }
            int sscan = lsum;
#pragma unroll
            for (int o = 1; o < 32; o <<= 1) {
                int vv = __shfl_up_sync(0xffffffffu, sscan, o);
                if (lane >= o) sscan += vv;
            }
            int below = sscan - lsum;              // keys in lower lanes' bins
            if (below < Kp && Kp <= sscan) {       // crossing lane (unique)
                int cum = below, t = 0, nk = 0;
#pragma unroll
                for (int j = 0; j < 8; ++j) {
                    if (cum + local[j] >= Kp) { t = lane*8 + j; nk = Kp - cum; break; }
                    cum += local[j];
                }
                redi[40] = t; redi[41] = nk;
            }
        }
        __syncthreads();
        pref = (pref << 8) | (unsigned)redi[40];
    }
    unsigned long long T = pref;    // exact K-th smallest key

    // ---- compact ascending by token index ----
    int f0 = key[base4+0] <= T, f1 = key[base4+1] <= T,
        f2 = key[base4+2] <= T, f3 = key[base4+3] <= T;
    int tot = f0 + f1 + f2 + f3;
    int x = tot;
#pragma unroll
    for (int o = 1; o < 32; o <<= 1) {
        int y = __shfl_up_sync(0xffffffffu, x, o);
        if (lane >= o) x += y;
    }
    if (lane == 31) redi[wid] = x;
    __syncthreads();
    if (wid == 0) {
        int y = redi[lane];
        int z = y;
#pragma unroll
        for (int o = 1; o < 32; o <<= 1) {
            int w2 = __shfl_up_sync(0xffffffffu, z, o);
            if (lane >= o) z += w2;
        }
        redi[32 + lane] = z - y;   // exclusive
    }
    __syncthreads();
    int off = redi[32 + wid] + (x - tot);

    int flags[4] = {f0, f1, f2, f3};
#pragma unroll
    for (int qq = 0; qq < 4; ++qq) {
        if (flags[qq]) {
            int idx = base4 + qq;
            int pos = b*KK + off;
            g_selidx[pos] = idx;
            out_idx[pos]  = (float)idx;
            g_gate[pos]   = 1.0f + 0.1f * (1.0f / (1.0f + expf(-sc[idx])));
            ++off;
        }
    }
}

// ---------------- Kernel 6: gather + gate ----------------
__global__ void __launch_bounds__(256) gather_kernel(
    const float* __restrict__ tokens, float* __restrict__ out_sel)
{
    int bk  = blockIdx.x;          // b*K + kk
    int b   = bk >> 11;
    int idx = g_selidx[bk];
    float gate = g_gate[bk];
    const float4* src = (const float4*)(tokens + ((size_t)(b*TT + idx)) * (JJ*CC));
    float4* dst = (float4*)(out_sel + (size_t)bk * (JJ*CC));
#pragma unroll 2
    for (int i = threadIdx.x; i < (JJ*CC)/4; i += 256) {
        float4 v = src[i];
        v.x *= gate; v.y *= gate; v.z *= gate; v.w *= gate;
        dst[i] = v;
    }
}

// ---------------- launch ----------------
extern "C" void kernel_launch(void* const* d_in, const int* in_sizes, int n_in,
                              void* d_out, int out_size)
{
    const float* tokens = (const float*)d_in[0];
    const float* ln_w   = (const float*)d_in[1];
    const float* ln_b   = (const float*)d_in[2];
    const float* W1     = (const float*)d_in[3];
    const float* b1     = (const float*)d_in[4];
    const float* W2     = (const float*)d_in[5];
    const float* b2     = (const float*)d_in[6];

    float* out        = (float*)d_out;
    float* out_sel    = out;                       // [B,K,J,C]
    float* out_idx    = out + SEL_ELEMS;           // [B,K]
    float* out_scores = out_idx + IDX_ELEMS;       // [B,T]

    cudaFuncSetAttribute(mlp_kernel,
        cudaFuncAttributeMaxDynamicSharedMemorySize, MLP_SMEM);
    cudaFuncSetAttribute(topk_kernel,
        cudaFuncAttributeMaxDynamicSharedMemorySize, TOPK_SMEM);

    mean_ln_kernel<<<BT/8, 256>>>(tokens, ln_w, ln_b);
    gc_final_kernel<<<BB, 1024>>>();
    split_w_kernel<<<256, 256>>>(W1);
    mlp_kernel<<<BT/64, 512, MLP_SMEM>>>(b1, W2, b2);   // 4th launch -> ncu capture
    topk_kernel<<<BB, 1024, TOPK_SMEM>>>(out_idx, out_scores);
    gather_kernel<<<BB*KK, 256>>>(tokens, out_sel);
}